// round 13
// baseline (speedup 1.0000x reference)
#include <cuda_runtime.h>

// Gaussian splatting via tile-owned gather (8x8x16 tiles), precomputed
// per-gaussian exp tables, single-warp accumulate CTAs.
//  K0 (memset): zero per-tile counters.
//  K1 params: per-gaussian bbox -> packed params.
//  K2 scatter: 18 threads per gaussian, <=1 atomic each; bucket entry =
//     {packed window offsets (tile-ready), gid*TABW}.
//  K3 tables: one thread per slot, padded exp tables (coalesced STG).
//     Per gaussian: x[32] y[32] z[48] = 112 floats; x/y anchored mn-8,
//     z anchored mn-16; zeros outside bbox; intensity folded into z.
//  K4 accum: ONE WARP per tile; thread owns two adjacent-y z-columns
//     (16 f32x2 accumulators); z-table broadcast LDS paid once per pair;
//     branchless packed f32x2 FMAs; direct float4 writeout.

#define NTILES 16384                   // 32 x 32 x 16
#define CAP 64
#define NMAX 65536
#define TABW 112

__device__ int    d_counts[NTILES];
__device__ int2   d_bucket[NTILES * CAP];   // {offpack, gid*TABW}
__device__ float4 d_params[2 * NMAX];       // [2g]={cx,cy,cz,inv2s2}; [2g+1]={I, mnpack, wpack, 0}
__device__ float  d_gtab[NMAX * TABW];

__device__ __forceinline__ void fma2(unsigned long long& d,
                                     unsigned long long a,
                                     unsigned long long b) {
    asm("fma.rn.f32x2 %0, %1, %2, %0;" : "+l"(d) : "l"(a), "l"(b));
}
__device__ __forceinline__ unsigned long long dup2(float x) {
    unsigned long long r;
    asm("mov.b64 %0, {%1, %1};" : "=l"(r) : "f"(x));
    return r;
}
__device__ __forceinline__ float2 unpack2(unsigned long long v) {
    float2 r;
    asm("mov.b64 {%0, %1}, %2;" : "=f"(r.x), "=f"(r.y) : "l"(v));
    return r;
}

__global__ void params_kernel(const float* __restrict__ centers,
                              const float* __restrict__ sigmas,
                              const float* __restrict__ intensities,
                              int n) {
    int g = blockIdx.x * blockDim.x + threadIdx.x;
    if (g >= n) return;

    float c3[3];
    c3[0] = __ldg(&centers[3 * g + 0]);
    c3[1] = __ldg(&centers[3 * g + 1]);
    c3[2] = __ldg(&centers[3 * g + 2]);
    const float sig   = __ldg(&sigmas[g]);
    const float inten = __ldg(&intensities[g]);

    const float cut    = 3.0f * sig * 255.0f;
    const float inv2s2 = 0.5f / (sig * sig);

    int mn[3], mx[3];
#pragma unroll
    for (int a = 0; a < 3; a++) {
        float cv = c3[a] * 255.0f;
        mn[a] = (int)floorf(fmaxf(cv - cut, 0.0f));
        mx[a] = (int)fminf(floorf(fminf(cv + cut, 255.0f)) + 1.0f, 256.0f);
    }

    int mnp = mn[0] | (mn[1] << 8) | (mn[2] << 16);
    int wp  = (mx[0] - mn[0]) | ((mx[1] - mn[1]) << 8) | ((mx[2] - mn[2]) << 16);

    d_params[2 * g + 0] = make_float4(c3[0], c3[1], c3[2], inv2s2);
    d_params[2 * g + 1] = make_float4(inten, __int_as_float(mnp), __int_as_float(wp), 0.0f);
}

// 18 threads per gaussian: slot s -> (dx, dy, dz) in 3x3x2.
__global__ void __launch_bounds__(256) scatter_kernel(int n) {
    int e = blockIdx.x * blockDim.x + threadIdx.x;
    int g = e / 18;
    if (g >= n) return;
    int s = e - g * 18;
    int dz = s & 1;
    int q  = s >> 1;
    int dx = q / 3;
    int dy = q - dx * 3;

    float4 p1 = d_params[2 * g + 1];
    int mnp = __float_as_int(p1.y);
    int wp  = __float_as_int(p1.z);
    int mnx = mnp & 255, mny = (mnp >> 8) & 255, mnz = (mnp >> 16) & 255;
    int wx  = wp & 255,  wy  = (wp >> 8) & 255,  wz  = (wp >> 16) & 255;

    int t0x = mnx >> 3, nx = ((mnx + wx - 1) >> 3) - t0x;
    int t0y = mny >> 3, ny = ((mny + wy - 1) >> 3) - t0y;
    int t0z = mnz >> 4, nz = ((mnz + wz - 1) >> 4) - t0z;

    if (dx <= nx && dy <= ny && dz <= nz) {
        int tx = t0x + dx, ty = t0y + dy, tz = t0z + dz;
        int t = (tx << 9) | (ty << 4) | tz;
        // Tile-ready table offsets (window start within padded tables).
        int offx = (tx << 3) - mnx + 8;
        int offy = (ty << 3) - mny + 8 + 32;
        int offz = (tz << 4) - mnz + 16 + 64;
        int pack = offx | (offy << 8) | (offz << 16);
        int slot = atomicAdd(&d_counts[t], 1);
        if (slot < CAP) d_bucket[t * CAP + slot] = make_int2(pack, g * TABW);
    }
}

__global__ void table_kernel(int n) {
    int e = blockIdx.x * blockDim.x + threadIdx.x;
    int g = e / TABW;
    if (g >= n) return;
    int s = e - g * TABW;

    float4 p0 = d_params[2 * g + 0];
    float4 p1 = d_params[2 * g + 1];

    int a   = (s < 32) ? 0 : ((s < 64) ? 1 : 2);
    int i   = s - ((a == 0) ? 0 : ((a == 1) ? 32 : 64));
    int pad = (a == 2) ? 16 : 8;

    float c = (a == 0) ? p0.x : ((a == 1) ? p0.y : p0.z);
    int mnp = __float_as_int(p1.y);
    int wp  = __float_as_int(p1.z);
    int mn_a = (mnp >> (8 * a)) & 255;
    int w_a  = (wp  >> (8 * a)) & 255;

    float v = 0.0f;
    if ((unsigned)(i - pad) < (unsigned)w_a) {
        float d = (float)(mn_a - pad + i) * (1.0f / 255.0f) - c;
        v = __expf(-d * d * p0.w);
        if (a == 2) v *= p1.x;
    }
    d_gtab[e] = v;
}

__global__ void __launch_bounds__(32) accum_kernel(float* __restrict__ out) {
    const int t   = blockIdx.x;
    const int tid = threadIdx.x;           // 0..31, single warp
    const int ox = (t >> 9) << 3;
    const int oy = ((t >> 4) & 31) << 3;
    const int oz = (t & 15) << 4;

    __shared__ int2 sbk[CAP];
    __shared__ __align__(16) float sx[CAP * 8];
    __shared__ __align__(16) float sy[CAP * 8];
    __shared__ __align__(16) float sz[CAP * 16];

    int cnt = d_counts[t];
    if (cnt > CAP) cnt = CAP;
    const int bucket_base = t * CAP;

    for (int i = tid; i < cnt; i += 32)
        sbk[i] = d_bucket[bucket_base + i];
    __syncwarp();

    // Window gathers: offsets are tile-ready (precomputed in scatter).
    const int n8 = cnt * 8;
    for (int e = tid; e < n8; e += 32) {
        int g = e >> 3, i = e & 7;
        int2 bk = sbk[g];
        sx[e] = d_gtab[bk.y + (bk.x & 255) + i];
    }
    for (int e = tid; e < n8; e += 32) {
        int g = e >> 3, i = e & 7;
        int2 bk = sbk[g];
        sy[e] = d_gtab[bk.y + ((bk.x >> 8) & 255) + i];
    }
    const int n16 = cnt * 16;
    for (int e = tid; e < n16; e += 32) {
        int g = e >> 4, i = e & 15;
        int2 bk = sbk[g];
        sz[e] = d_gtab[bk.y + ((bk.x >> 16) & 255) + i];
    }
    __syncwarp();

    // Thread owns two adjacent-y columns: (xi, 2*yp) and (xi, 2*yp+1).
    const int xi = tid >> 2;        // 0..7
    const int yp = tid & 3;         // 0..3
    const float* sxp = &sx[xi];
    const float* syp = &sy[2 * yp];

    unsigned long long accA[8], accB[8];
#pragma unroll
    for (int p = 0; p < 8; p++) { accA[p] = 0ULL; accB[p] = 0ULL; }

#pragma unroll 2
    for (int g = 0; g < cnt; g++) {
        float  sxv = sxp[g * 8];
        float2 syv = *(const float2*)&syp[g * 8];
        unsigned long long wA = dup2(sxv * syv.x);
        unsigned long long wB = dup2(sxv * syv.y);
        const ulonglong2* ez = (const ulonglong2*)&sz[g * 16];
        ulonglong2 z0 = ez[0], z1 = ez[1], z2 = ez[2], z3 = ez[3];
        fma2(accA[0], wA, z0.x);  fma2(accB[0], wB, z0.x);
        fma2(accA[1], wA, z0.y);  fma2(accB[1], wB, z0.y);
        fma2(accA[2], wA, z1.x);  fma2(accB[2], wB, z1.x);
        fma2(accA[3], wA, z1.y);  fma2(accB[3], wB, z1.y);
        fma2(accA[4], wA, z2.x);  fma2(accB[4], wB, z2.x);
        fma2(accA[5], wA, z2.y);  fma2(accB[5], wB, z2.y);
        fma2(accA[6], wA, z3.x);  fma2(accB[6], wB, z3.x);
        fma2(accA[7], wA, z3.y);  fma2(accB[7], wB, z3.y);
    }

    const int addrA = (ox + xi) * 65536 + (oy + 2 * yp) * 256 + oz;
    const int addrB = addrA + 256;
#pragma unroll
    for (int q = 0; q < 4; q++) {
        float2 a0 = unpack2(accA[2 * q + 0]);
        float2 a1 = unpack2(accA[2 * q + 1]);
        *(float4*)&out[addrA + 4 * q] = make_float4(a0.x, a0.y, a1.x, a1.y);
    }
#pragma unroll
    for (int q = 0; q < 4; q++) {
        float2 b0 = unpack2(accB[2 * q + 0]);
        float2 b1 = unpack2(accB[2 * q + 1]);
        *(float4*)&out[addrB + 4 * q] = make_float4(b0.x, b0.y, b1.x, b1.y);
    }
}

extern "C" void kernel_launch(void* const* d_in, const int* in_sizes, int n_in,
                              void* d_out, int out_size) {
    const float* centers = (const float*)d_in[0];
    const float* sigmas = (const float*)d_in[1];
    const float* intensities = (const float*)d_in[2];
    float* out = (float*)d_out;
    const int n = in_sizes[1];

    void* counts_ptr = nullptr;
    cudaGetSymbolAddress(&counts_ptr, d_counts);
    cudaMemsetAsync(counts_ptr, 0, NTILES * sizeof(int), 0);

    params_kernel<<<(n + 255) / 256, 256>>>(centers, sigmas, intensities, n);
    scatter_kernel<<<(n * 18 + 255) / 256, 256>>>(n);
    table_kernel<<<(n * TABW + 255) / 256, 256>>>(n);
    accum_kernel<<<NTILES, 32>>>(out);
}